// round 9
// baseline (speedup 1.0000x reference)
#include <cuda_runtime.h>
#include <math.h>

#define BB 32
#define HH 128
#define WW 128
#define CC 64
#define MX 16
#define MY 16
#define NK 17

typedef unsigned long long u64;

__device__ __forceinline__ u64 pk(float a, float b) {
    u64 r; asm("mov.b64 %0, {%1,%2};" : "=l"(r) : "f"(a), "f"(b)); return r;
}
__device__ __forceinline__ float2 upk(u64 v) {
    float2 f; asm("mov.b64 {%0,%1}, %2;" : "=f"(f.x), "=f"(f.y) : "l"(v)); return f;
}
__device__ __forceinline__ void fma2(u64 &d, u64 a, u64 b) {
    asm("fma.rn.f32x2 %0, %1, %2, %0;" : "+l"(d) : "l"(a), "l"(b));
}
__device__ __forceinline__ void add2(u64 &d, u64 a) {
    asm("add.rn.f32x2 %0, %0, %1;" : "+l"(d) : "l"(a));
}
__device__ __forceinline__ float fast_tanh(float x) {
    float t; asm("tanh.approx.f32 %0, %1;" : "=f"(t) : "f"(x)); return t;
}
__device__ __forceinline__ unsigned sptr(const void* p) {
    unsigned a;
    asm("{ .reg .u64 t; cvta.to.shared.u64 t, %1; cvt.u32.u64 %0, t; }" : "=r"(a) : "l"(p));
    return a;
}
#define CP16(s, g) asm volatile("cp.async.cg.shared.global [%0], [%1], 16;" :: "r"(s), "l"(g))

// ---------------- scratch ----------------
__device__ __align__(16) u64 g_X1[BB*NK*WW*CC];        // (re,im)
__device__ __align__(16) u64 g_Y [BB*32*MY*CC];        // (re,im)
__device__ __align__(16) u64 g_G [BB*MY*32*CC];        // (re,im) [b][ky][r][c]
__device__ __align__(16) float g_Mre[BB*MY*HH*CC];
__device__ __align__(16) float g_Mim[BB*MY*HH*CC];

// twiddle tables
__device__ __align__(16) u64 g_TA2[HH*18];             // [h][k] pk(cos,-sin), k=17 pad 0
__device__ __align__(16) u64 g_TBc[WW*MY];             // pk(c,c)
__device__ __align__(16) u64 g_TBs[WW*MY];             // pk(s,s)
__device__ __align__(16) ulonglong2 g_TP[128];         // {pk(c,c), pk(s,s)}
__device__ __align__(16) u64 g_TC2[WW*8];
__device__ __align__(16) u64 g_TS2[WW*8];

// ---------------- init ----------------
__global__ void k_init() {
    int t = blockIdx.x * blockDim.x + threadIdx.x;
    int stride = gridDim.x * blockDim.x;
    const float STEP = 6.28318530717958647692f / 128.0f;

    for (int i = t; i < HH*18; i += stride) {
        int h = i / 18, k = i % 18;
        if (k < 17) {
            int m = (k * h) & 127;
            float s, c; sincosf(STEP * (float)m, &s, &c);
            g_TA2[i] = pk(c, -s);
        } else g_TA2[i] = 0ull;
    }
    for (int i = t; i < WW*MY; i += stride) {
        int w = i / MY, ky = i % MY;
        int m = (ky * w) & 127;
        float s, c; sincosf(STEP * (float)m, &s, &c);
        g_TBc[i] = pk(c, c);
        g_TBs[i] = pk(s, s);
    }
    for (int i = t; i < 128; i += stride) {
        float s, c; sincosf(STEP * (float)i, &s, &c);
        g_TP[i].x = pk(c, c);
        g_TP[i].y = pk(s, s);
    }
    for (int i = t; i < WW*8; i += stride) {
        int w = i / 8, j = i % 8;
        int k0 = 2*j, k1 = 2*j + 1;
        float s0, c0, s1, c1;
        sincosf(STEP * (float)((k0 * w) & 127), &s0, &c0);
        sincosf(STEP * (float)((k1 * w) & 127), &s1, &c1);
        float f0 = ((k0 == 0) ? 1.f : 2.f) / 16384.f;
        float f1 = 2.f / 16384.f;
        g_TC2[i] = pk(f0 * c0, f1 * c1);
        g_TS2[i] = pk(-f0 * s0, -f1 * s1);
    }
}

// ---------------- stage A: partial DFT over h, h-pair symmetry, 2x unroll ----------------
__global__ __launch_bounds__(256) void k_stageA(const float* __restrict__ x) {
    __shared__ ulonglong2 sTA[64*9];              // rows h = 0..63
    int b = blockIdx.y, wt = blockIdx.x;
    const ulonglong2* gTA = (const ulonglong2*)g_TA2;
    for (int i = threadIdx.x; i < 64*9; i += 256) sTA[i] = gTA[i];
    __syncthreads();

    int tid = threadIdx.x;
    int c = tid & 63;
    int w = wt*4 + (tid >> 6);
    const float* xb = x + (size_t)b * HH * WW * CC + (size_t)w * CC + c;

    u64 a[18];
    {   // h = 0 and h = 64 singles
        float x0  = xb[0];
        float x64 = xb[(size_t)64*WW*CC];
        float ep = x0 + x64, em = x0 - x64;
#pragma unroll
        for (int k = 0; k < 17; k++) a[k] = pk((k & 1) ? em : ep, 0.f);
        a[17] = 0ull;
    }

    float va0 = xb[(size_t)1*WW*CC];
    float vb0 = xb[(size_t)127*WW*CC];
    float va1 = xb[(size_t)2*WW*CC];
    float vb1 = xb[(size_t)126*WW*CC];

    for (int p = 1; p <= 61; p += 2) {
        float na0 = xb[(size_t)(p+2)*WW*CC];
        float nb0 = xb[(size_t)(126-p)*WW*CC];
        float na1 = 0.f, nb1 = 0.f;
        if (p < 61) {
            na1 = xb[(size_t)(p+3)*WW*CC];
            nb1 = xb[(size_t)(125-p)*WW*CC];
        }
        u64 sd0 = pk(va0 + vb0, va0 - vb0);
        u64 sd1 = pk(va1 + vb1, va1 - vb1);
#pragma unroll
        for (int q = 0; q < 9; q++) {
            ulonglong2 tw = sTA[p*9 + q];
            fma2(a[2*q],   sd0, tw.x);
            fma2(a[2*q+1], sd0, tw.y);
        }
#pragma unroll
        for (int q = 0; q < 9; q++) {
            ulonglong2 tw = sTA[(p+1)*9 + q];
            fma2(a[2*q],   sd1, tw.x);
            fma2(a[2*q+1], sd1, tw.y);
        }
        va0 = na0; vb0 = nb0; va1 = na1; vb1 = nb1;
    }
    {   // tail p = 63
        u64 sd = pk(va0 + vb0, va0 - vb0);
#pragma unroll
        for (int q = 0; q < 9; q++) {
            ulonglong2 tw = sTA[63*9 + q];
            fma2(a[2*q],   sd, tw.x);
            fma2(a[2*q+1], sd, tw.y);
        }
    }
#pragma unroll
    for (int k = 0; k < 17; k++)
        g_X1[((size_t)(b*NK + k)*WW + w)*CC + c] = a[k];
}

// ---------------- stage B: partial DFT over w, w-pair symmetry ----------------
__global__ __launch_bounds__(256) void k_stageB() {
    __shared__ __align__(16) u64 sCC[64*MY];
    __shared__ __align__(16) u64 sSS[64*MY];
    int b = blockIdx.y, k = blockIdx.x;   // 0..16
    for (int i = threadIdx.x; i < 64*MY; i += 256) { sCC[i] = g_TBc[i]; sSS[i] = g_TBs[i]; }
    __syncthreads();

    int tid = threadIdx.x;
    int c  = tid & 63;
    int kg = tid >> 6;
    const u64* xp = g_X1 + (size_t)(b*NK + k)*WW*CC;

    u64 P[4], Q[4] = {0,0,0,0};
    {
        float2 f0  = upk(xp[c]);
        float2 f64 = upk(xp[64*CC + c]);
#pragma unroll
        for (int j = 0; j < 4; j++) {
            int ky = kg*4 + j;
            float sx = (ky & 1) ? -f64.x : f64.x;
            float sy = (ky & 1) ? -f64.y : f64.y;
            P[j] = pk(f0.x + sx, f0.y + sy);
        }
    }

    for (int w = 1; w < 64; w++) {
        float2 fa = upk(xp[w*CC + c]);
        float2 fb = upk(xp[(128 - w)*CC + c]);
        u64 Vs  = pk(fa.x + fb.x, fa.y + fb.y);
        u64 VdA = pk(fa.y - fb.y, fb.x - fa.x);
        const ulonglong2* cp = (const ulonglong2*)&sCC[w*MY + kg*4];
        const ulonglong2* sp = (const ulonglong2*)&sSS[w*MY + kg*4];
        ulonglong2 c01 = cp[0], c23 = cp[1];
        ulonglong2 s01 = sp[0], s23 = sp[1];
        fma2(P[0], Vs, c01.x);  fma2(Q[0], VdA, s01.x);
        fma2(P[1], Vs, c01.y);  fma2(Q[1], VdA, s01.y);
        fma2(P[2], Vs, c23.x);  fma2(Q[2], VdA, s23.x);
        fma2(P[3], Vs, c23.y);  fma2(Q[3], VdA, s23.y);
    }
    if (k < 16) {
#pragma unroll
        for (int j = 0; j < 4; j++) {
            int ky = kg*4 + j;
            float2 p = upk(P[j]), q = upk(Q[j]);
            g_Y[((size_t)(b*32 + k)*MY + ky)*CC + c] = pk(p.x + q.x, p.y + q.y);
        }
    }
    if (k >= 1) {
        int r2 = 32 - k;
#pragma unroll
        for (int j = 0; j < 4; j++) {
            int ky = kg*4 + j;
            float2 p = upk(P[j]), q = upk(Q[j]);
            g_Y[((size_t)(b*32 + r2)*MY + ky)*CC + c] = pk(p.x - q.x, q.y - p.y);
        }
    }
}

// ---------------- stage C: complex mode mixing, cp.async W staging ----------------
__global__ __launch_bounds__(256) void k_stageC(const float* __restrict__ w1r,
                                                const float* __restrict__ w1i,
                                                const float* __restrict__ w2r,
                                                const float* __restrict__ w2i) {
    extern __shared__ __align__(16) float smem[];
    float* sWr  = smem;
    float* sWi  = smem + 4096;
    float* sYre = smem + 8192;
    float* sYim = sYre + 64*36;

    int ky = blockIdx.x, r = blockIdx.y;
    int tid = threadIdx.x;

    const float* __restrict__ Wr;
    const float* __restrict__ Wi;
    if (r < 16) {
        Wr = w1r + (size_t)((r*16 + ky)*64)*64;
        Wi = w1i + (size_t)((r*16 + ky)*64)*64;
    } else {
        Wr = w2r + (size_t)(((r-16)*16 + ky)*64)*64;
        Wi = w2i + (size_t)(((r-16)*16 + ky)*64)*64;
    }

    {
        unsigned swr = sptr(sWr), swi = sptr(sWi);
#pragma unroll
        for (int j = 0; j < 4; j++) {
            int i = tid + j*256;
            CP16(swr + i*16, Wr + i*4);
            CP16(swi + i*16, Wi + i*4);
        }
        asm volatile("cp.async.commit_group;");
    }

    for (int idx = tid; idx < 2048; idx += 256) {
        int bb = idx >> 6, cc2 = idx & 63;
        float2 f = upk(g_Y[((size_t)(bb*32 + r)*MY + ky)*CC + cc2]);
        sYre[cc2*36 + bb] = f.x;
        sYim[cc2*36 + bb] = f.y;
    }
    asm volatile("cp.async.wait_group 0;");
    __syncthreads();

    int o  = tid & 63;
    int bg = tid >> 6;
    u64 P1[4] = {0,0,0,0}, P2[4] = {0,0,0,0}, P3[4] = {0,0,0,0}, P4[4] = {0,0,0,0};

    for (int i = 0; i < 64; i++) {
        float wr = sWr[i*64 + o];
        float wi = sWi[i*64 + o];
        u64 wrp = pk(wr, wr);
        u64 wip = pk(wi, wi);
        const ulonglong2* yrp = (const ulonglong2*)&sYre[i*36 + bg*8];
        const ulonglong2* yip = (const ulonglong2*)&sYim[i*36 + bg*8];
        ulonglong2 yr01 = yrp[0], yr23 = yrp[1];
        ulonglong2 yi01 = yip[0], yi23 = yip[1];
        fma2(P1[0], yr01.x, wrp);  fma2(P2[0], yi01.x, wip);
        fma2(P3[0], yr01.x, wip);  fma2(P4[0], yi01.x, wrp);
        fma2(P1[1], yr01.y, wrp);  fma2(P2[1], yi01.y, wip);
        fma2(P3[1], yr01.y, wip);  fma2(P4[1], yi01.y, wrp);
        fma2(P1[2], yr23.x, wrp);  fma2(P2[2], yi23.x, wip);
        fma2(P3[2], yr23.x, wip);  fma2(P4[2], yi23.x, wrp);
        fma2(P1[3], yr23.y, wrp);  fma2(P2[3], yi23.y, wip);
        fma2(P3[3], yr23.y, wip);  fma2(P4[3], yi23.y, wrp);
    }
#pragma unroll
    for (int bp = 0; bp < 4; bp++) {
        int bb = bg*8 + bp*2;
        float2 p1 = upk(P1[bp]), p2 = upk(P2[bp]);
        float2 p3 = upk(P3[bp]), p4 = upk(P4[bp]);
        g_G[((size_t)(bb    *MY + ky)*32 + r)*CC + o] = pk(p1.x - p2.x, p3.x + p4.x);
        g_G[((size_t)((bb+1)*MY + ky)*32 + r)*CC + o] = pk(p1.y - p2.y, p3.y + p4.y);
    }
}

// ---------------- stage D1: inverse DFT over h, r-pair + h-mirror symmetry ----------------
__global__ __launch_bounds__(512) void k_stageD1() {
    __shared__ __align__(16) u64 sG[32*64];
    __shared__ ulonglong2 sTP[128];
    int ky = blockIdx.x, b = blockIdx.y;
    int tid = threadIdx.x;
    for (int i = tid; i < 2048; i += 512)
        sG[i] = g_G[((size_t)(b*MY + ky)*32 + (i >> 6))*CC + (i & 63)];
    for (int i = tid; i < 128; i += 512) sTP[i] = g_TP[i];
    __syncthreads();

    int c  = tid & 63;
    int hg = tid >> 6;
    int hbase = 1 + hg*8;

    u64 mc[8], ms[8];
#pragma unroll
    for (int q = 0; q < 8; q++) { mc[q] = 0ull; ms[q] = 0ull; }
    u64 g0 = sG[c];
    u64 Ssum = 0ull;

#pragma unroll
    for (int r = 1; r <= 16; r++) {
        u64 S, Dp;
        if (r < 16) {
            float2 ga = upk(sG[r*64 + c]);
            float2 gb = upk(sG[(32 - r)*64 + c]);
            S  = pk(ga.x + gb.x, ga.y + gb.y);
            Dp = pk(gb.y - ga.y, ga.x - gb.x);
        } else {
            float2 g = upk(sG[16*64 + c]);
            S  = pk(g.x, g.y);
            Dp = pk(g.y, -g.x);
        }
        if (hg == 0) add2(Ssum, S);
        int mm = (r * hbase) & 127;
#pragma unroll
        for (int hh = 0; hh < 8; hh++) {
            ulonglong2 t = sTP[mm];
            fma2(mc[hh], S,  t.x);
            fma2(ms[hh], Dp, t.y);
            mm = (mm + r) & 127;
        }
    }

    float2 fg0 = upk(g0);
    size_t base = (size_t)(b*MY + ky)*HH;
#pragma unroll
    for (int hh = 0; hh < 8; hh++) {
        int h = hbase + hh;
        float2 c2 = upk(mc[hh]), s2 = upk(ms[hh]);
        float tre = fg0.x + c2.x, tim = fg0.y + c2.y;
        size_t off = (base + h)*CC + c;
        g_Mre[off] = tre + s2.x;
        g_Mim[off] = tim + s2.y;
        if (h < 64) {
            size_t off2 = (base + 128 - h)*CC + c;
            g_Mre[off2] = tre - s2.x;
            g_Mim[off2] = tim - s2.y;
        }
    }
    if (hg == 0) {
        float2 fs = upk(Ssum);
        size_t off = base*CC + c;
        g_Mre[off] = fg0.x + fs.x;
        g_Mim[off] = fg0.y + fs.y;
    }
}

// ---------------- stage E: transposed outer-product dense + spectral + GELU ----------------
// dynamic smem: xTu[64][66] u64 | sTC[1024] u64 | sTS[1024] u64 | sKd[4096] float
__global__ __launch_bounds__(256, 3) void k_stageE(const float* __restrict__ x,
                                                   const float* __restrict__ Kd,
                                                   const float* __restrict__ bias,
                                                   float* __restrict__ out) {
    extern __shared__ __align__(16) u64 dsm[];
    u64*   xTu = dsm;                       // 64*66 = 4224 u64
    u64*   sTC = dsm + 4224;                // 1024 u64
    u64*   sTS = sTC + 1024;                // 1024 u64
    float* sKd = (float*)(sTS + 1024);      // 4096 floats

    int h = blockIdx.x, b = blockIdx.y;
    int tid = threadIdx.x;
    int c  = tid & 63;
    int wg = tid >> 6;

    for (int i = tid; i < 1024; i += 256) { sTC[i] = g_TC2[i]; sTS[i] = g_TS2[i]; }
    for (int i = tid; i < 4096; i += 256) sKd[i] = Kd[i];

    const float* xrow = x + ((size_t)(b*HH + h)*WW)*CC;
    // transpose-stage x row: xTu[chan][pair] = pk(x[2pp][chan], x[2pp+1][chan])
    for (int idx = tid; idx < 4096; idx += 256) {
        int c2 = idx & 63, pp = idx >> 6;
        float e = xrow[(size_t)(2*pp)*64 + c2];
        float o = xrow[(size_t)(2*pp+1)*64 + c2];
        xTu[c2*66 + pp] = pk(e, o);
    }

    u64 R2[8], I2[8];
#pragma unroll
    for (int j = 0; j < 8; j++) {
        size_t o0 = ((size_t)(b*MY + 2*j    )*HH + h)*CC + c;
        size_t o1 = ((size_t)(b*MY + 2*j + 1)*HH + h)*CC + c;
        R2[j] = pk(g_Mre[o0], g_Mre[o1]);
        I2[j] = pk(g_Mim[o0], g_Mim[o1]);
    }
    float bc = bias[c];
    float* orow = out + ((size_t)(b*HH + h)*WW)*CC;
    __syncthreads();

    // dense: outer product over input channel i; x reads warp-broadcast
    u64 acc[16];
#pragma unroll
    for (int j = 0; j < 16; j++) acc[j] = pk(bc, bc);

    int pbase = wg*16;
    for (int i = 0; i < 64; i++) {
        float kd = sKd[i*64 + c];
        u64 kdp = pk(kd, kd);
        const ulonglong2* xq = (const ulonglong2*)&xTu[i*66 + pbase];
#pragma unroll
        for (int t = 0; t < 8; t++) {
            ulonglong2 q = xq[t];
            fma2(acc[2*t],     q.x, kdp);
            fma2(acc[2*t + 1], q.y, kdp);
        }
    }

    const float gk = 0.7978845608028654f;
    const float gb2 = 0.044715f;

#pragma unroll 4
    for (int j = 0; j < 16; j++) {
        int pp = pbase + j;
        int w0 = 2*pp, w1 = w0 + 1;
        float2 dd = upk(acc[j]);                    // dense+bias for (w0, w1)
        float2 xv = upk(xTu[c*66 + pp]);            // residuals

        // spectral pixel w0
        u64 yA = 0ull, yB = 0ull;
        {
            const ulonglong2* tcp = (const ulonglong2*)&sTC[w0*8];
            const ulonglong2* tsp = (const ulonglong2*)&sTS[w0*8];
#pragma unroll
            for (int t = 0; t < 4; t++) {
                ulonglong2 tc = tcp[t];
                ulonglong2 ts = tsp[t];
                fma2(yA, R2[2*t],     tc.x);
                fma2(yB, R2[2*t + 1], tc.y);
                fma2(yA, I2[2*t],     ts.x);
                fma2(yB, I2[2*t + 1], ts.y);
            }
        }
        float2 s0 = upk(yA), s1 = upk(yB);
        float u0 = xv.x + dd.x + s0.x + s0.y + s1.x + s1.y;

        // spectral pixel w1
        u64 zA = 0ull, zB = 0ull;
        {
            const ulonglong2* tcp = (const ulonglong2*)&sTC[w1*8];
            const ulonglong2* tsp = (const ulonglong2*)&sTS[w1*8];
#pragma unroll
            for (int t = 0; t < 4; t++) {
                ulonglong2 tc = tcp[t];
                ulonglong2 ts = tsp[t];
                fma2(zA, R2[2*t],     tc.x);
                fma2(zB, R2[2*t + 1], tc.y);
                fma2(zA, I2[2*t],     ts.x);
                fma2(zB, I2[2*t + 1], ts.y);
            }
        }
        float2 t0 = upk(zA), t1 = upk(zB);
        float u1 = xv.y + dd.y + t0.x + t0.y + t1.x + t1.y;

        float v0 = u0*u0*u0;
        float g0f = fast_tanh(gk*(u0 + gb2*v0));
        orow[(size_t)w0*64 + c] = 0.5f*u0*(1.f + g0f);
        float v1 = u1*u1*u1;
        float g1f = fast_tanh(gk*(u1 + gb2*v1));
        orow[(size_t)w1*64 + c] = 0.5f*u1*(1.f + g1f);
    }
}

// ---------------- launch ----------------
extern "C" void kernel_launch(void* const* d_in, const int* in_sizes, int n_in,
                              void* d_out, int out_size) {
    const float* x    = (const float*)d_in[0];
    const float* w1r  = (const float*)d_in[1];
    const float* w1i  = (const float*)d_in[2];
    const float* w2r  = (const float*)d_in[3];
    const float* w2i  = (const float*)d_in[4];
    const float* Kd   = (const float*)d_in[5];
    const float* bias = (const float*)d_in[6];
    float* out = (float*)d_out;

    const int C_SMEM = (4096 + 4096 + 64*36 + 64*36) * 4;        // 51200 bytes
    const int E_SMEM = (4224 + 1024 + 1024) * 8 + 4096 * 4;      // 66560 bytes
    static int attr_set = 0;
    if (!attr_set) {
        cudaFuncSetAttribute(k_stageC, cudaFuncAttributeMaxDynamicSharedMemorySize, C_SMEM);
        cudaFuncSetAttribute(k_stageE, cudaFuncAttributeMaxDynamicSharedMemorySize, E_SMEM);
        attr_set = 1;
    }

    k_init<<<64, 256>>>();
    k_stageA<<<dim3(32, 32), 256>>>(x);
    k_stageB<<<dim3(17, 32), 256>>>();
    k_stageC<<<dim3(16, 32), 256, C_SMEM>>>(w1r, w1i, w2r, w2i);
    k_stageD1<<<dim3(16, 32), 512>>>();
    k_stageE<<<dim3(128, 32), 256, E_SMEM>>>(x, Kd, bias, out);
}

// round 10
// speedup vs baseline: 1.2853x; 1.2853x over previous
#include <cuda_runtime.h>
#include <math.h>

#define BB 32
#define HH 128
#define WW 128
#define CC 64
#define MX 16
#define MY 16
#define NK 17

typedef unsigned long long u64;

__device__ __forceinline__ u64 pk(float a, float b) {
    u64 r; asm("mov.b64 %0, {%1,%2};" : "=l"(r) : "f"(a), "f"(b)); return r;
}
__device__ __forceinline__ float2 upk(u64 v) {
    float2 f; asm("mov.b64 {%0,%1}, %2;" : "=f"(f.x), "=f"(f.y) : "l"(v)); return f;
}
__device__ __forceinline__ void fma2(u64 &d, u64 a, u64 b) {
    asm("fma.rn.f32x2 %0, %1, %2, %0;" : "+l"(d) : "l"(a), "l"(b));
}
__device__ __forceinline__ void add2(u64 &d, u64 a) {
    asm("add.rn.f32x2 %0, %0, %1;" : "+l"(d) : "l"(a));
}
__device__ __forceinline__ float fast_tanh(float x) {
    float t; asm("tanh.approx.f32 %0, %1;" : "=f"(t) : "f"(x)); return t;
}
__device__ __forceinline__ unsigned sptr(const void* p) {
    unsigned a;
    asm("{ .reg .u64 t; cvta.to.shared.u64 t, %1; cvt.u32.u64 %0, t; }" : "=r"(a) : "l"(p));
    return a;
}
#define CP16(s, g) asm volatile("cp.async.cg.shared.global [%0], [%1], 16;" :: "r"(s), "l"(g))

// ---------------- scratch ----------------
__device__ __align__(16) u64 g_X1[BB*NK*WW*CC];        // (re,im)
__device__ __align__(16) u64 g_Y [BB*32*MY*CC];        // (re,im)
__device__ __align__(16) u64 g_G [BB*MY*32*CC];        // (re,im) [b][ky][r][c]
__device__ __align__(16) float g_Mre[BB*MY*HH*CC];
__device__ __align__(16) float g_Mim[BB*MY*HH*CC];

// twiddle tables
__device__ __align__(16) u64 g_TA2[HH*18];             // [h][k] pk(cos,-sin), k=17 pad 0
__device__ __align__(16) u64 g_TBc[WW*MY];             // pk(c,c)
__device__ __align__(16) u64 g_TBs[WW*MY];             // pk(s,s)
__device__ __align__(16) ulonglong2 g_TP[128];         // {pk(c,c), pk(s,s)}
__device__ __align__(16) u64 g_TC2[WW*8];
__device__ __align__(16) u64 g_TS2[WW*8];

// ---------------- init ----------------
__global__ void k_init() {
    int t = blockIdx.x * blockDim.x + threadIdx.x;
    int stride = gridDim.x * blockDim.x;
    const float STEP = 6.28318530717958647692f / 128.0f;

    for (int i = t; i < HH*18; i += stride) {
        int h = i / 18, k = i % 18;
        if (k < 17) {
            int m = (k * h) & 127;
            float s, c; sincosf(STEP * (float)m, &s, &c);
            g_TA2[i] = pk(c, -s);
        } else g_TA2[i] = 0ull;
    }
    for (int i = t; i < WW*MY; i += stride) {
        int w = i / MY, ky = i % MY;
        int m = (ky * w) & 127;
        float s, c; sincosf(STEP * (float)m, &s, &c);
        g_TBc[i] = pk(c, c);
        g_TBs[i] = pk(s, s);
    }
    for (int i = t; i < 128; i += stride) {
        float s, c; sincosf(STEP * (float)i, &s, &c);
        g_TP[i].x = pk(c, c);
        g_TP[i].y = pk(s, s);
    }
    for (int i = t; i < WW*8; i += stride) {
        int w = i / 8, j = i % 8;
        int k0 = 2*j, k1 = 2*j + 1;
        float s0, c0, s1, c1;
        sincosf(STEP * (float)((k0 * w) & 127), &s0, &c0);
        sincosf(STEP * (float)((k1 * w) & 127), &s1, &c1);
        float f0 = ((k0 == 0) ? 1.f : 2.f) / 16384.f;
        float f1 = 2.f / 16384.f;
        g_TC2[i] = pk(f0 * c0, f1 * c1);
        g_TS2[i] = pk(-f0 * s0, -f1 * s1);
    }
}

// ---------------- stage A: partial DFT over h, h-pair symmetry, 2x unroll ----------------
__global__ __launch_bounds__(256) void k_stageA(const float* __restrict__ x) {
    __shared__ ulonglong2 sTA[64*9];              // rows h = 0..63
    int b = blockIdx.y, wt = blockIdx.x;
    const ulonglong2* gTA = (const ulonglong2*)g_TA2;
    for (int i = threadIdx.x; i < 64*9; i += 256) sTA[i] = gTA[i];
    __syncthreads();

    int tid = threadIdx.x;
    int c = tid & 63;
    int w = wt*4 + (tid >> 6);
    const float* xb = x + (size_t)b * HH * WW * CC + (size_t)w * CC + c;

    u64 a[18];
    {   // h = 0 and h = 64 singles
        float x0  = xb[0];
        float x64 = xb[(size_t)64*WW*CC];
        float ep = x0 + x64, em = x0 - x64;
#pragma unroll
        for (int k = 0; k < 17; k++) a[k] = pk((k & 1) ? em : ep, 0.f);
        a[17] = 0ull;
    }

    float va0 = xb[(size_t)1*WW*CC];
    float vb0 = xb[(size_t)127*WW*CC];
    float va1 = xb[(size_t)2*WW*CC];
    float vb1 = xb[(size_t)126*WW*CC];

    for (int p = 1; p <= 61; p += 2) {
        float na0 = xb[(size_t)(p+2)*WW*CC];
        float nb0 = xb[(size_t)(126-p)*WW*CC];
        float na1 = 0.f, nb1 = 0.f;
        if (p < 61) {
            na1 = xb[(size_t)(p+3)*WW*CC];
            nb1 = xb[(size_t)(125-p)*WW*CC];
        }
        u64 sd0 = pk(va0 + vb0, va0 - vb0);
        u64 sd1 = pk(va1 + vb1, va1 - vb1);
#pragma unroll
        for (int q = 0; q < 9; q++) {
            ulonglong2 tw = sTA[p*9 + q];
            fma2(a[2*q],   sd0, tw.x);
            fma2(a[2*q+1], sd0, tw.y);
        }
#pragma unroll
        for (int q = 0; q < 9; q++) {
            ulonglong2 tw = sTA[(p+1)*9 + q];
            fma2(a[2*q],   sd1, tw.x);
            fma2(a[2*q+1], sd1, tw.y);
        }
        va0 = na0; vb0 = nb0; va1 = na1; vb1 = nb1;
    }
    {   // tail p = 63
        u64 sd = pk(va0 + vb0, va0 - vb0);
#pragma unroll
        for (int q = 0; q < 9; q++) {
            ulonglong2 tw = sTA[63*9 + q];
            fma2(a[2*q],   sd, tw.x);
            fma2(a[2*q+1], sd, tw.y);
        }
    }
#pragma unroll
    for (int k = 0; k < 17; k++)
        g_X1[((size_t)(b*NK + k)*WW + w)*CC + c] = a[k];
}

// ---------------- stage B: partial DFT over w, w-pair symmetry ----------------
__global__ __launch_bounds__(256) void k_stageB() {
    __shared__ __align__(16) u64 sCC[64*MY];
    __shared__ __align__(16) u64 sSS[64*MY];
    int b = blockIdx.y, k = blockIdx.x;   // 0..16
    for (int i = threadIdx.x; i < 64*MY; i += 256) { sCC[i] = g_TBc[i]; sSS[i] = g_TBs[i]; }
    __syncthreads();

    int tid = threadIdx.x;
    int c  = tid & 63;
    int kg = tid >> 6;
    const u64* xp = g_X1 + (size_t)(b*NK + k)*WW*CC;

    u64 P[4], Q[4] = {0,0,0,0};
    {
        float2 f0  = upk(xp[c]);
        float2 f64 = upk(xp[64*CC + c]);
#pragma unroll
        for (int j = 0; j < 4; j++) {
            int ky = kg*4 + j;
            float sx = (ky & 1) ? -f64.x : f64.x;
            float sy = (ky & 1) ? -f64.y : f64.y;
            P[j] = pk(f0.x + sx, f0.y + sy);
        }
    }

    for (int w = 1; w < 64; w++) {
        float2 fa = upk(xp[w*CC + c]);
        float2 fb = upk(xp[(128 - w)*CC + c]);
        u64 Vs  = pk(fa.x + fb.x, fa.y + fb.y);
        u64 VdA = pk(fa.y - fb.y, fb.x - fa.x);
        const ulonglong2* cp = (const ulonglong2*)&sCC[w*MY + kg*4];
        const ulonglong2* sp = (const ulonglong2*)&sSS[w*MY + kg*4];
        ulonglong2 c01 = cp[0], c23 = cp[1];
        ulonglong2 s01 = sp[0], s23 = sp[1];
        fma2(P[0], Vs, c01.x);  fma2(Q[0], VdA, s01.x);
        fma2(P[1], Vs, c01.y);  fma2(Q[1], VdA, s01.y);
        fma2(P[2], Vs, c23.x);  fma2(Q[2], VdA, s23.x);
        fma2(P[3], Vs, c23.y);  fma2(Q[3], VdA, s23.y);
    }
    if (k < 16) {
#pragma unroll
        for (int j = 0; j < 4; j++) {
            int ky = kg*4 + j;
            float2 p = upk(P[j]), q = upk(Q[j]);
            g_Y[((size_t)(b*32 + k)*MY + ky)*CC + c] = pk(p.x + q.x, p.y + q.y);
        }
    }
    if (k >= 1) {
        int r2 = 32 - k;
#pragma unroll
        for (int j = 0; j < 4; j++) {
            int ky = kg*4 + j;
            float2 p = upk(P[j]), q = upk(Q[j]);
            g_Y[((size_t)(b*32 + r2)*MY + ky)*CC + c] = pk(p.x - q.x, q.y - p.y);
        }
    }
}

// ---------------- stage C: complex mode mixing, cp.async W staging ----------------
__global__ __launch_bounds__(256) void k_stageC(const float* __restrict__ w1r,
                                                const float* __restrict__ w1i,
                                                const float* __restrict__ w2r,
                                                const float* __restrict__ w2i) {
    extern __shared__ __align__(16) float smem[];
    float* sWr  = smem;
    float* sWi  = smem + 4096;
    float* sYre = smem + 8192;
    float* sYim = sYre + 64*36;

    int ky = blockIdx.x, r = blockIdx.y;
    int tid = threadIdx.x;

    const float* __restrict__ Wr;
    const float* __restrict__ Wi;
    if (r < 16) {
        Wr = w1r + (size_t)((r*16 + ky)*64)*64;
        Wi = w1i + (size_t)((r*16 + ky)*64)*64;
    } else {
        Wr = w2r + (size_t)(((r-16)*16 + ky)*64)*64;
        Wi = w2i + (size_t)(((r-16)*16 + ky)*64)*64;
    }

    {
        unsigned swr = sptr(sWr), swi = sptr(sWi);
#pragma unroll
        for (int j = 0; j < 4; j++) {
            int i = tid + j*256;
            CP16(swr + i*16, Wr + i*4);
            CP16(swi + i*16, Wi + i*4);
        }
        asm volatile("cp.async.commit_group;");
    }

    for (int idx = tid; idx < 2048; idx += 256) {
        int bb = idx >> 6, cc2 = idx & 63;
        float2 f = upk(g_Y[((size_t)(bb*32 + r)*MY + ky)*CC + cc2]);
        sYre[cc2*36 + bb] = f.x;
        sYim[cc2*36 + bb] = f.y;
    }
    asm volatile("cp.async.wait_group 0;");
    __syncthreads();

    int o  = tid & 63;
    int bg = tid >> 6;
    u64 P1[4] = {0,0,0,0}, P2[4] = {0,0,0,0}, P3[4] = {0,0,0,0}, P4[4] = {0,0,0,0};

    for (int i = 0; i < 64; i++) {
        float wr = sWr[i*64 + o];
        float wi = sWi[i*64 + o];
        u64 wrp = pk(wr, wr);
        u64 wip = pk(wi, wi);
        const ulonglong2* yrp = (const ulonglong2*)&sYre[i*36 + bg*8];
        const ulonglong2* yip = (const ulonglong2*)&sYim[i*36 + bg*8];
        ulonglong2 yr01 = yrp[0], yr23 = yrp[1];
        ulonglong2 yi01 = yip[0], yi23 = yip[1];
        fma2(P1[0], yr01.x, wrp);  fma2(P2[0], yi01.x, wip);
        fma2(P3[0], yr01.x, wip);  fma2(P4[0], yi01.x, wrp);
        fma2(P1[1], yr01.y, wrp);  fma2(P2[1], yi01.y, wip);
        fma2(P3[1], yr01.y, wip);  fma2(P4[1], yi01.y, wrp);
        fma2(P1[2], yr23.x, wrp);  fma2(P2[2], yi23.x, wip);
        fma2(P3[2], yr23.x, wip);  fma2(P4[2], yi23.x, wrp);
        fma2(P1[3], yr23.y, wrp);  fma2(P2[3], yi23.y, wip);
        fma2(P3[3], yr23.y, wip);  fma2(P4[3], yi23.y, wrp);
    }
#pragma unroll
    for (int bp = 0; bp < 4; bp++) {
        int bb = bg*8 + bp*2;
        float2 p1 = upk(P1[bp]), p2 = upk(P2[bp]);
        float2 p3 = upk(P3[bp]), p4 = upk(P4[bp]);
        g_G[((size_t)(bb    *MY + ky)*32 + r)*CC + o] = pk(p1.x - p2.x, p3.x + p4.x);
        g_G[((size_t)((bb+1)*MY + ky)*32 + r)*CC + o] = pk(p1.y - p2.y, p3.y + p4.y);
    }
}

// ---------------- stage D1: inverse DFT over h, r-pair + h-mirror symmetry ----------------
__global__ __launch_bounds__(512) void k_stageD1() {
    __shared__ __align__(16) u64 sG[32*64];
    __shared__ ulonglong2 sTP[128];
    int ky = blockIdx.x, b = blockIdx.y;
    int tid = threadIdx.x;
    for (int i = tid; i < 2048; i += 512)
        sG[i] = g_G[((size_t)(b*MY + ky)*32 + (i >> 6))*CC + (i & 63)];
    for (int i = tid; i < 128; i += 512) sTP[i] = g_TP[i];
    __syncthreads();

    int c  = tid & 63;
    int hg = tid >> 6;
    int hbase = 1 + hg*8;

    u64 mc[8], ms[8];
#pragma unroll
    for (int q = 0; q < 8; q++) { mc[q] = 0ull; ms[q] = 0ull; }
    u64 g0 = sG[c];
    u64 Ssum = 0ull;

#pragma unroll
    for (int r = 1; r <= 16; r++) {
        u64 S, Dp;
        if (r < 16) {
            float2 ga = upk(sG[r*64 + c]);
            float2 gb = upk(sG[(32 - r)*64 + c]);
            S  = pk(ga.x + gb.x, ga.y + gb.y);
            Dp = pk(gb.y - ga.y, ga.x - gb.x);
        } else {
            float2 g = upk(sG[16*64 + c]);
            S  = pk(g.x, g.y);
            Dp = pk(g.y, -g.x);
        }
        if (hg == 0) add2(Ssum, S);
        int mm = (r * hbase) & 127;
#pragma unroll
        for (int hh = 0; hh < 8; hh++) {
            ulonglong2 t = sTP[mm];
            fma2(mc[hh], S,  t.x);
            fma2(ms[hh], Dp, t.y);
            mm = (mm + r) & 127;
        }
    }

    float2 fg0 = upk(g0);
    size_t base = (size_t)(b*MY + ky)*HH;
#pragma unroll
    for (int hh = 0; hh < 8; hh++) {
        int h = hbase + hh;
        float2 c2 = upk(mc[hh]), s2 = upk(ms[hh]);
        float tre = fg0.x + c2.x, tim = fg0.y + c2.y;
        size_t off = (base + h)*CC + c;
        g_Mre[off] = tre + s2.x;
        g_Mim[off] = tim + s2.y;
        if (h < 64) {
            size_t off2 = (base + 128 - h)*CC + c;
            g_Mre[off2] = tre - s2.x;
            g_Mim[off2] = tim - s2.y;
        }
    }
    if (hg == 0) {
        float2 fs = upk(Ssum);
        size_t off = base*CC + c;
        g_Mre[off] = fg0.x + fs.x;
        g_Mim[off] = fg0.y + fs.y;
    }
}

// ---------------- stage E: inverse DFT over w + dense + bias + residual + GELU, 4 chains ----------------
__global__ __launch_bounds__(256, 2) void k_stageE(const float* __restrict__ x,
                                                   const float* __restrict__ Kd,
                                                   const float* __restrict__ bias,
                                                   float* __restrict__ out) {
    __shared__ __align__(16) u64 xs2[64*32];
    __shared__ __align__(16) u64 sTC[WW*8];
    __shared__ __align__(16) u64 sTS[WW*8];
    int h = blockIdx.x, b = blockIdx.y;
    int tid = threadIdx.x;
    int c  = tid & 63;
    int wg = tid >> 6;

    for (int i = tid; i < WW*8; i += 256) { sTC[i] = g_TC2[i]; sTS[i] = g_TS2[i]; }

    u64 Kp[32];
#pragma unroll
    for (int i = 0; i < 32; i++)
        Kp[i] = pk(Kd[(2*i)*64 + c], Kd[(2*i+1)*64 + c]);

    u64 R2[8], I2[8];
#pragma unroll
    for (int j = 0; j < 8; j++) {
        size_t o0 = ((size_t)(b*MY + 2*j    )*HH + h)*CC + c;
        size_t o1 = ((size_t)(b*MY + 2*j + 1)*HH + h)*CC + c;
        R2[j] = pk(g_Mre[o0], g_Mre[o1]);
        I2[j] = pk(g_Mim[o0], g_Mim[o1]);
    }
    float bc = bias[c];
    const float* xrow = x   + ((size_t)(b*HH + h)*WW)*CC;
    float*       orow = out + ((size_t)(b*HH + h)*WW)*CC;

    for (int half = 0; half < 2; half++) {
        __syncthreads();
        for (int i = tid; i < 2048; i += 256)
            xs2[i] = ((const u64*)(xrow + half*64*CC))[i];
        __syncthreads();

        for (int ww = 0; ww < 16; ww++) {
            int w = wg*16 + ww;
            int wglob = half*64 + w;
            u64 acc0 = pk(bc, 0.f);
            u64 acc1 = 0ull, acc2 = 0ull, acc3 = 0ull;
            const ulonglong2* xv = (const ulonglong2*)&xs2[w*32];
#pragma unroll
            for (int t = 0; t < 8; t++) {
                ulonglong2 qa = xv[2*t];
                ulonglong2 qb = xv[2*t + 1];
                fma2(acc0, qa.x, Kp[4*t]);
                fma2(acc1, qa.y, Kp[4*t + 1]);
                fma2(acc2, qb.x, Kp[4*t + 2]);
                fma2(acc3, qb.y, Kp[4*t + 3]);
            }
            const ulonglong2* tcp = (const ulonglong2*)&sTC[wglob*8];
            const ulonglong2* tsp = (const ulonglong2*)&sTS[wglob*8];
#pragma unroll
            for (int t = 0; t < 2; t++) {
                ulonglong2 tc0 = tcp[2*t];
                ulonglong2 tc1 = tcp[2*t + 1];
                ulonglong2 ts0 = tsp[2*t];
                ulonglong2 ts1 = tsp[2*t + 1];
                fma2(acc0, R2[4*t],     tc0.x);
                fma2(acc1, R2[4*t + 1], tc0.y);
                fma2(acc2, R2[4*t + 2], tc1.x);
                fma2(acc3, R2[4*t + 3], tc1.y);
                fma2(acc0, I2[4*t],     ts0.x);
                fma2(acc1, I2[4*t + 1], ts0.y);
                fma2(acc2, I2[4*t + 2], ts1.x);
                fma2(acc3, I2[4*t + 3], ts1.y);
            }
            float2 s0 = upk(acc0), s1 = upk(acc1), s2 = upk(acc2), s3 = upk(acc3);
            float xval = ((const float*)xs2)[w*64 + c];
            float u = xval + ((s0.x + s0.y) + (s1.x + s1.y)) + ((s2.x + s2.y) + (s3.x + s3.y));
            float u3 = u*u*u;
            float t = fast_tanh(0.7978845608028654f*(u + 0.044715f*u3));
            orow[(size_t)wglob*64 + c] = 0.5f*u*(1.f + t);
        }
    }
}

// ---------------- launch ----------------
extern "C" void kernel_launch(void* const* d_in, const int* in_sizes, int n_in,
                              void* d_out, int out_size) {
    const float* x    = (const float*)d_in[0];
    const float* w1r  = (const float*)d_in[1];
    const float* w1i  = (const float*)d_in[2];
    const float* w2r  = (const float*)d_in[3];
    const float* w2i  = (const float*)d_in[4];
    const float* Kd   = (const float*)d_in[5];
    const float* bias = (const float*)d_in[6];
    float* out = (float*)d_out;

    const int C_SMEM = (4096 + 4096 + 64*36 + 64*36) * 4;   // 51200 bytes
    static int attr_set = 0;
    if (!attr_set) {
        cudaFuncSetAttribute(k_stageC, cudaFuncAttributeMaxDynamicSharedMemorySize, C_SMEM);
        attr_set = 1;
    }

    k_init<<<64, 256>>>();
    k_stageA<<<dim3(32, 32), 256>>>(x);
    k_stageB<<<dim3(17, 32), 256>>>();
    k_stageC<<<dim3(16, 32), 256, C_SMEM>>>(w1r, w1i, w2r, w2i);
    k_stageD1<<<dim3(16, 32), 512>>>();
    k_stageE<<<dim3(128, 32), 256>>>(x, Kd, bias, out);
}

// round 11
// speedup vs baseline: 1.5014x; 1.1681x over previous
#include <cuda_runtime.h>
#include <math.h>

#define BB 32
#define HH 128
#define WW 128
#define CC 64
#define MX 16
#define MY 16
#define NK 17

typedef unsigned long long u64;

__device__ __forceinline__ u64 pk(float a, float b) {
    u64 r; asm("mov.b64 %0, {%1,%2};" : "=l"(r) : "f"(a), "f"(b)); return r;
}
__device__ __forceinline__ float2 upk(u64 v) {
    float2 f; asm("mov.b64 {%0,%1}, %2;" : "=f"(f.x), "=f"(f.y) : "l"(v)); return f;
}
__device__ __forceinline__ void fma2(u64 &d, u64 a, u64 b) {
    asm("fma.rn.f32x2 %0, %1, %2, %0;" : "+l"(d) : "l"(a), "l"(b));
}
__device__ __forceinline__ void add2(u64 &d, u64 a) {
    asm("add.rn.f32x2 %0, %0, %1;" : "+l"(d) : "l"(a));
}
__device__ __forceinline__ float fast_tanh(float x) {
    float t; asm("tanh.approx.f32 %0, %1;" : "=f"(t) : "f"(x)); return t;
}
__device__ __forceinline__ unsigned sptr(const void* p) {
    unsigned a;
    asm("{ .reg .u64 t; cvta.to.shared.u64 t, %1; cvt.u32.u64 %0, t; }" : "=r"(a) : "l"(p));
    return a;
}
#define CP16(s, g) asm volatile("cp.async.cg.shared.global [%0], [%1], 16;" :: "r"(s), "l"(g))

// ---------------- scratch ----------------
__device__ __align__(16) u64 g_X1[BB*NK*WW*CC];        // (re,im)
__device__ __align__(16) u64 g_Y [BB*32*MY*CC];        // (re,im)
__device__ __align__(16) u64 g_G [BB*MY*32*CC];        // (re,im) [b][ky][r][c]
__device__ __align__(16) float g_Mre[BB*MY*HH*CC];
__device__ __align__(16) float g_Mim[BB*MY*HH*CC];

// twiddle tables
__device__ __align__(16) u64 g_TA2[HH*18];             // [h][k] pk(cos,-sin), k=17 pad 0
__device__ __align__(16) u64 g_TBc[WW*MY];             // pk(c,c)
__device__ __align__(16) u64 g_TBs[WW*MY];             // pk(s,s)
__device__ __align__(16) ulonglong2 g_TP[128];         // {pk(c,c), pk(s,s)}
__device__ __align__(16) u64 g_TC2[WW*8];
__device__ __align__(16) u64 g_TS2[WW*8];

// ---------------- init ----------------
__global__ void k_init() {
    int t = blockIdx.x * blockDim.x + threadIdx.x;
    int stride = gridDim.x * blockDim.x;
    const float STEP = 6.28318530717958647692f / 128.0f;

    for (int i = t; i < HH*18; i += stride) {
        int h = i / 18, k = i % 18;
        if (k < 17) {
            int m = (k * h) & 127;
            float s, c; sincosf(STEP * (float)m, &s, &c);
            g_TA2[i] = pk(c, -s);
        } else g_TA2[i] = 0ull;
    }
    for (int i = t; i < WW*MY; i += stride) {
        int w = i / MY, ky = i % MY;
        int m = (ky * w) & 127;
        float s, c; sincosf(STEP * (float)m, &s, &c);
        g_TBc[i] = pk(c, c);
        g_TBs[i] = pk(s, s);
    }
    for (int i = t; i < 128; i += stride) {
        float s, c; sincosf(STEP * (float)i, &s, &c);
        g_TP[i].x = pk(c, c);
        g_TP[i].y = pk(s, s);
    }
    for (int i = t; i < WW*8; i += stride) {
        int w = i / 8, j = i % 8;
        int k0 = 2*j, k1 = 2*j + 1;
        float s0, c0, s1, c1;
        sincosf(STEP * (float)((k0 * w) & 127), &s0, &c0);
        sincosf(STEP * (float)((k1 * w) & 127), &s1, &c1);
        float f0 = ((k0 == 0) ? 1.f : 2.f) / 16384.f;
        float f1 = 2.f / 16384.f;
        g_TC2[i] = pk(f0 * c0, f1 * c1);
        g_TS2[i] = pk(-f0 * s0, -f1 * s1);
    }
}

// ---------------- stage A: partial DFT over h, h-pair symmetry, 2x unroll ----------------
__global__ __launch_bounds__(256) void k_stageA(const float* __restrict__ x) {
    __shared__ ulonglong2 sTA[64*9];              // rows h = 0..63
    int b = blockIdx.y, wt = blockIdx.x;
    const ulonglong2* gTA = (const ulonglong2*)g_TA2;
    for (int i = threadIdx.x; i < 64*9; i += 256) sTA[i] = gTA[i];
    __syncthreads();

    int tid = threadIdx.x;
    int c = tid & 63;
    int w = wt*4 + (tid >> 6);
    const float* xb = x + (size_t)b * HH * WW * CC + (size_t)w * CC + c;

    u64 a[18];
    {   // h = 0 and h = 64 singles
        float x0  = xb[0];
        float x64 = xb[(size_t)64*WW*CC];
        float ep = x0 + x64, em = x0 - x64;
#pragma unroll
        for (int k = 0; k < 17; k++) a[k] = pk((k & 1) ? em : ep, 0.f);
        a[17] = 0ull;
    }

    float va0 = xb[(size_t)1*WW*CC];
    float vb0 = xb[(size_t)127*WW*CC];
    float va1 = xb[(size_t)2*WW*CC];
    float vb1 = xb[(size_t)126*WW*CC];

    for (int p = 1; p <= 61; p += 2) {
        float na0 = xb[(size_t)(p+2)*WW*CC];
        float nb0 = xb[(size_t)(126-p)*WW*CC];
        float na1 = 0.f, nb1 = 0.f;
        if (p < 61) {
            na1 = xb[(size_t)(p+3)*WW*CC];
            nb1 = xb[(size_t)(125-p)*WW*CC];
        }
        u64 sd0 = pk(va0 + vb0, va0 - vb0);
        u64 sd1 = pk(va1 + vb1, va1 - vb1);
#pragma unroll
        for (int q = 0; q < 9; q++) {
            ulonglong2 tw = sTA[p*9 + q];
            fma2(a[2*q],   sd0, tw.x);
            fma2(a[2*q+1], sd0, tw.y);
        }
#pragma unroll
        for (int q = 0; q < 9; q++) {
            ulonglong2 tw = sTA[(p+1)*9 + q];
            fma2(a[2*q],   sd1, tw.x);
            fma2(a[2*q+1], sd1, tw.y);
        }
        va0 = na0; vb0 = nb0; va1 = na1; vb1 = nb1;
    }
    {   // tail p = 63
        u64 sd = pk(va0 + vb0, va0 - vb0);
#pragma unroll
        for (int q = 0; q < 9; q++) {
            ulonglong2 tw = sTA[63*9 + q];
            fma2(a[2*q],   sd, tw.x);
            fma2(a[2*q+1], sd, tw.y);
        }
    }
#pragma unroll
    for (int k = 0; k < 17; k++)
        g_X1[((size_t)(b*NK + k)*WW + w)*CC + c] = a[k];
}

// ---------------- stage B: partial DFT over w, w-pair symmetry ----------------
__global__ __launch_bounds__(256) void k_stageB() {
    __shared__ __align__(16) u64 sCC[64*MY];
    __shared__ __align__(16) u64 sSS[64*MY];
    int b = blockIdx.y, k = blockIdx.x;   // 0..16
    for (int i = threadIdx.x; i < 64*MY; i += 256) { sCC[i] = g_TBc[i]; sSS[i] = g_TBs[i]; }
    __syncthreads();

    int tid = threadIdx.x;
    int c  = tid & 63;
    int kg = tid >> 6;
    const u64* xp = g_X1 + (size_t)(b*NK + k)*WW*CC;

    u64 P[4], Q[4] = {0,0,0,0};
    {
        float2 f0  = upk(xp[c]);
        float2 f64 = upk(xp[64*CC + c]);
#pragma unroll
        for (int j = 0; j < 4; j++) {
            int ky = kg*4 + j;
            float sx = (ky & 1) ? -f64.x : f64.x;
            float sy = (ky & 1) ? -f64.y : f64.y;
            P[j] = pk(f0.x + sx, f0.y + sy);
        }
    }

    for (int w = 1; w < 64; w++) {
        float2 fa = upk(xp[w*CC + c]);
        float2 fb = upk(xp[(128 - w)*CC + c]);
        u64 Vs  = pk(fa.x + fb.x, fa.y + fb.y);
        u64 VdA = pk(fa.y - fb.y, fb.x - fa.x);
        const ulonglong2* cp = (const ulonglong2*)&sCC[w*MY + kg*4];
        const ulonglong2* sp = (const ulonglong2*)&sSS[w*MY + kg*4];
        ulonglong2 c01 = cp[0], c23 = cp[1];
        ulonglong2 s01 = sp[0], s23 = sp[1];
        fma2(P[0], Vs, c01.x);  fma2(Q[0], VdA, s01.x);
        fma2(P[1], Vs, c01.y);  fma2(Q[1], VdA, s01.y);
        fma2(P[2], Vs, c23.x);  fma2(Q[2], VdA, s23.x);
        fma2(P[3], Vs, c23.y);  fma2(Q[3], VdA, s23.y);
    }
    if (k < 16) {
#pragma unroll
        for (int j = 0; j < 4; j++) {
            int ky = kg*4 + j;
            float2 p = upk(P[j]), q = upk(Q[j]);
            g_Y[((size_t)(b*32 + k)*MY + ky)*CC + c] = pk(p.x + q.x, p.y + q.y);
        }
    }
    if (k >= 1) {
        int r2 = 32 - k;
#pragma unroll
        for (int j = 0; j < 4; j++) {
            int ky = kg*4 + j;
            float2 p = upk(P[j]), q = upk(Q[j]);
            g_Y[((size_t)(b*32 + r2)*MY + ky)*CC + c] = pk(p.x - q.x, q.y - p.y);
        }
    }
}

// ---------------- stage C: complex mode mixing, cp.async W staging, batch-split 2x ----------------
// dynamic smem: sWr[4096] | sWi[4096] | sYre[64*20] | sYim[64*20]  (floats)
__global__ __launch_bounds__(256) void k_stageC(const float* __restrict__ w1r,
                                                const float* __restrict__ w1i,
                                                const float* __restrict__ w2r,
                                                const float* __restrict__ w2i) {
    extern __shared__ __align__(16) float smem[];
    float* sWr  = smem;
    float* sWi  = smem + 4096;
    float* sYre = smem + 8192;
    float* sYim = sYre + 64*20;

    int ky = blockIdx.x, r = blockIdx.y;
    int bh = blockIdx.z;                 // batch half: 0 or 1
    int tid = threadIdx.x;

    const float* __restrict__ Wr;
    const float* __restrict__ Wi;
    if (r < 16) {
        Wr = w1r + (size_t)((r*16 + ky)*64)*64;
        Wi = w1i + (size_t)((r*16 + ky)*64)*64;
    } else {
        Wr = w2r + (size_t)(((r-16)*16 + ky)*64)*64;
        Wi = w2i + (size_t)(((r-16)*16 + ky)*64)*64;
    }

    {
        unsigned swr = sptr(sWr), swi = sptr(sWi);
#pragma unroll
        for (int j = 0; j < 4; j++) {
            int i = tid + j*256;
            CP16(swr + i*16, Wr + i*4);
            CP16(swi + i*16, Wi + i*4);
        }
        asm volatile("cp.async.commit_group;");
    }

    // Y transpose: 16 batches x 64 channels
    for (int idx = tid; idx < 1024; idx += 256) {
        int bb = idx >> 6, cc2 = idx & 63;
        float2 f = upk(g_Y[((size_t)((bh*16 + bb)*32 + r)*MY + ky)*CC + cc2]);
        sYre[cc2*20 + bb] = f.x;
        sYim[cc2*20 + bb] = f.y;
    }
    asm volatile("cp.async.wait_group 0;");
    __syncthreads();

    int o  = tid & 63;
    int bg = tid >> 6;                   // 4 groups, each 4 batches (2 pairs)
    u64 P1[2] = {0,0}, P2[2] = {0,0}, P3[2] = {0,0}, P4[2] = {0,0};

    for (int i = 0; i < 64; i++) {
        float wr = sWr[i*64 + o];
        float wi = sWi[i*64 + o];
        u64 wrp = pk(wr, wr);
        u64 wip = pk(wi, wi);
        ulonglong2 yr = *(const ulonglong2*)&sYre[i*20 + bg*4];
        ulonglong2 yi = *(const ulonglong2*)&sYim[i*20 + bg*4];
        fma2(P1[0], yr.x, wrp);  fma2(P2[0], yi.x, wip);
        fma2(P3[0], yr.x, wip);  fma2(P4[0], yi.x, wrp);
        fma2(P1[1], yr.y, wrp);  fma2(P2[1], yi.y, wip);
        fma2(P3[1], yr.y, wip);  fma2(P4[1], yi.y, wrp);
    }
#pragma unroll
    for (int bp = 0; bp < 2; bp++) {
        int bb = bh*16 + bg*4 + bp*2;
        float2 p1 = upk(P1[bp]), p2 = upk(P2[bp]);
        float2 p3 = upk(P3[bp]), p4 = upk(P4[bp]);
        g_G[((size_t)(bb    *MY + ky)*32 + r)*CC + o] = pk(p1.x - p2.x, p3.x + p4.x);
        g_G[((size_t)((bb+1)*MY + ky)*32 + r)*CC + o] = pk(p1.y - p2.y, p3.y + p4.y);
    }
}

// ---------------- stage D1: inverse DFT over h, r-pair + h-mirror symmetry ----------------
__global__ __launch_bounds__(512) void k_stageD1() {
    __shared__ __align__(16) u64 sG[32*64];
    __shared__ ulonglong2 sTP[128];
    int ky = blockIdx.x, b = blockIdx.y;
    int tid = threadIdx.x;
    for (int i = tid; i < 2048; i += 512)
        sG[i] = g_G[((size_t)(b*MY + ky)*32 + (i >> 6))*CC + (i & 63)];
    for (int i = tid; i < 128; i += 512) sTP[i] = g_TP[i];
    __syncthreads();

    int c  = tid & 63;
    int hg = tid >> 6;
    int hbase = 1 + hg*8;

    u64 mc[8], ms[8];
#pragma unroll
    for (int q = 0; q < 8; q++) { mc[q] = 0ull; ms[q] = 0ull; }
    u64 g0 = sG[c];
    u64 Ssum = 0ull;

#pragma unroll
    for (int r = 1; r <= 16; r++) {
        u64 S, Dp;
        if (r < 16) {
            float2 ga = upk(sG[r*64 + c]);
            float2 gb = upk(sG[(32 - r)*64 + c]);
            S  = pk(ga.x + gb.x, ga.y + gb.y);
            Dp = pk(gb.y - ga.y, ga.x - gb.x);
        } else {
            float2 g = upk(sG[16*64 + c]);
            S  = pk(g.x, g.y);
            Dp = pk(g.y, -g.x);
        }
        if (hg == 0) add2(Ssum, S);
        int mm = (r * hbase) & 127;
#pragma unroll
        for (int hh = 0; hh < 8; hh++) {
            ulonglong2 t = sTP[mm];
            fma2(mc[hh], S,  t.x);
            fma2(ms[hh], Dp, t.y);
            mm = (mm + r) & 127;
        }
    }

    float2 fg0 = upk(g0);
    size_t base = (size_t)(b*MY + ky)*HH;
#pragma unroll
    for (int hh = 0; hh < 8; hh++) {
        int h = hbase + hh;
        float2 c2 = upk(mc[hh]), s2 = upk(ms[hh]);
        float tre = fg0.x + c2.x, tim = fg0.y + c2.y;
        size_t off = (base + h)*CC + c;
        g_Mre[off] = tre + s2.x;
        g_Mim[off] = tim + s2.y;
        if (h < 64) {
            size_t off2 = (base + 128 - h)*CC + c;
            g_Mre[off2] = tre - s2.x;
            g_Mim[off2] = tim - s2.y;
        }
    }
    if (hg == 0) {
        float2 fs = upk(Ssum);
        size_t off = base*CC + c;
        g_Mre[off] = fg0.x + fs.x;
        g_Mim[off] = fg0.y + fs.y;
    }
}

// ---------------- stage E: full-row cp.async staging + 2-chain dense/spectral + GELU ----------------
// dynamic smem: xs2[4096] u64 | sTC[1024] u64 | sTS[1024] u64 = 49152 bytes
__global__ __launch_bounds__(256, 2) void k_stageE(const float* __restrict__ x,
                                                   const float* __restrict__ Kd,
                                                   const float* __restrict__ bias,
                                                   float* __restrict__ out) {
    extern __shared__ __align__(16) u64 dsm[];
    u64* xs2 = dsm;              // 4096 u64 = full 128-pixel row
    u64* sTC = dsm + 4096;       // 1024 u64
    u64* sTS = sTC + 1024;       // 1024 u64

    int h = blockIdx.x, b = blockIdx.y;
    int tid = threadIdx.x;
    int c  = tid & 63;
    int wg = tid >> 6;

    const float* xrow = x   + ((size_t)(b*HH + h)*WW)*CC;
    float*       orow = out + ((size_t)(b*HH + h)*WW)*CC;

    // fire-and-forget staging of x row + twiddle tables
    {
        unsigned sx = sptr(xs2);
#pragma unroll
        for (int j = 0; j < 8; j++) {
            int i = tid + j*256;
            CP16(sx + i*16, xrow + i*4);
        }
        unsigned stc = sptr(sTC), sts = sptr(sTS);
#pragma unroll
        for (int j = 0; j < 2; j++) {
            int i = tid + j*256;
            CP16(stc + i*16, (const float*)g_TC2 + i*4);
            CP16(sts + i*16, (const float*)g_TS2 + i*4);
        }
        asm volatile("cp.async.commit_group;");
    }

    // overlapped register prefetch: Kp, R2/I2, bias
    u64 Kp[32];
#pragma unroll
    for (int i = 0; i < 32; i++)
        Kp[i] = pk(Kd[(2*i)*64 + c], Kd[(2*i+1)*64 + c]);

    u64 R2[8], I2[8];
#pragma unroll
    for (int j = 0; j < 8; j++) {
        size_t o0 = ((size_t)(b*MY + 2*j    )*HH + h)*CC + c;
        size_t o1 = ((size_t)(b*MY + 2*j + 1)*HH + h)*CC + c;
        R2[j] = pk(g_Mre[o0], g_Mre[o1]);
        I2[j] = pk(g_Mim[o0], g_Mim[o1]);
    }
    float bc = bias[c];

    asm volatile("cp.async.wait_group 0;");
    __syncthreads();

    for (int ww = 0; ww < 32; ww++) {
        int w = wg*32 + ww;
        u64 acc0 = pk(bc, 0.f);
        u64 acc1 = 0ull;
        const ulonglong2* xv = (const ulonglong2*)&xs2[w*32];
#pragma unroll
        for (int t = 0; t < 16; t++) {
            ulonglong2 q = xv[t];
            fma2(acc0, q.x, Kp[2*t]);
            fma2(acc1, q.y, Kp[2*t + 1]);
        }
        const ulonglong2* tcp = (const ulonglong2*)&sTC[w*8];
        const ulonglong2* tsp = (const ulonglong2*)&sTS[w*8];
#pragma unroll
        for (int t = 0; t < 4; t++) {
            ulonglong2 tc = tcp[t];
            ulonglong2 ts = tsp[t];
            fma2(acc0, R2[2*t],     tc.x);
            fma2(acc1, R2[2*t + 1], tc.y);
            fma2(acc0, I2[2*t],     ts.x);
            fma2(acc1, I2[2*t + 1], ts.y);
        }
        float2 s0 = upk(acc0), s1 = upk(acc1);
        float xval = ((const float*)xs2)[w*64 + c];
        float u = xval + s0.x + s0.y + s1.x + s1.y;
        float u3 = u*u*u;
        float t = fast_tanh(0.7978845608028654f*(u + 0.044715f*u3));
        orow[(size_t)w*64 + c] = 0.5f*u*(1.f + t);
    }
}

// ---------------- launch ----------------
extern "C" void kernel_launch(void* const* d_in, const int* in_sizes, int n_in,
                              void* d_out, int out_size) {
    const float* x    = (const float*)d_in[0];
    const float* w1r  = (const float*)d_in[1];
    const float* w1i  = (const float*)d_in[2];
    const float* w2r  = (const float*)d_in[3];
    const float* w2i  = (const float*)d_in[4];
    const float* Kd   = (const float*)d_in[5];
    const float* bias = (const float*)d_in[6];
    float* out = (float*)d_out;

    const int C_SMEM = (4096 + 4096 + 64*20 + 64*20) * 4;   // 43008 bytes
    const int E_SMEM = (4096 + 1024 + 1024) * 8;            // 49152 bytes
    static int attr_set = 0;
    if (!attr_set) {
        cudaFuncSetAttribute(k_stageC, cudaFuncAttributeMaxDynamicSharedMemorySize, C_SMEM);
        cudaFuncSetAttribute(k_stageE, cudaFuncAttributeMaxDynamicSharedMemorySize, E_SMEM);
        attr_set = 1;
    }

    k_init<<<64, 256>>>();
    k_stageA<<<dim3(32, 32), 256>>>(x);
    k_stageB<<<dim3(17, 32), 256>>>();
    k_stageC<<<dim3(16, 32, 2), 256, C_SMEM>>>(w1r, w1i, w2r, w2i);
    k_stageD1<<<dim3(16, 32), 512>>>();
    k_stageE<<<dim3(128, 32), 256, E_SMEM>>>(x, Kd, bias, out);
}